// round 9
// baseline (speedup 1.0000x reference)
#include <cuda_runtime.h>

#define L 2048
#define B 32
#define H 1024
#define H4 256
#define NB 148
#define NT 512

// Scratch (allocation-free rule: __device__ globals)
__device__ float g_vpart[64][B][H];      // 8 MB partials (16 g each)
__device__ float g_vq[4][B][H];          // 512 KB quarter-reduced v
__device__ float g_energy[B][L];         // 256 KB energies
__device__ unsigned g_maxu[B];           // monotone-encoded per-b max
__device__ unsigned g_bar;               // monotonic grid barrier counter

__device__ __forceinline__ unsigned enc_f(float x) {
    unsigned u = __float_as_uint(x);
    return (x >= 0.f) ? (u | 0x80000000u) : ~u;
}
__device__ __forceinline__ float dec_f(unsigned e) {
    return (e & 0x80000000u) ? __uint_as_float(e ^ 0x80000000u)
                             : __uint_as_float(~e);
}

// Software grid barrier: monotonic counter, no reset needed across replays.
// Phases are strictly ordered (release requires all NB arrivals), so each
// sync's arrivals occupy a contiguous [m*NB, (m+1)*NB) range.
__device__ __forceinline__ void grid_sync() {
    __syncthreads();
    if (threadIdx.x == 0) {
        __threadfence();
        const unsigned old = atomicAdd(&g_bar, 1u);
        const unsigned tgt = (old / NB + 1u) * NB;
        while (*(volatile unsigned*)&g_bar < tgt) __nanosleep(64);
        __threadfence();
    }
    __syncthreads();
}

__global__ void __launch_bounds__(NT, 1)
fused_attn(const float* __restrict__ hidden,
           const float* __restrict__ enc,
           const float* __restrict__ W,
           const int*   __restrict__ lengths,
           float* __restrict__ out) {
    const int tid = threadIdx.x;
    const int bid = blockIdx.x;

    __shared__ float  hsh[2][8][16];     // P1 hidden stage (1 KB)
    __shared__ float4 vsh[H4];           // P3 v row (4 KB)
    __shared__ float  red_s[16];         // P4 reduction

    // ---------------- Phase 1: v partials ----------------
    // unit u = (grp, hq): hq = float4 col 0..255, grp = bid*2 + (tid>>8):
    //   bq = grp & 3 (8 b's), gs = grp >> 2 (16 g's). Blocks 0..127 active.
    if (bid == 0 && tid < B) g_maxu[tid] = 0u;   // reset encoded -inf (pre-sync)

    if (bid < 128) {
        if (tid < 256) {   // stage hidden: 2 groups x 8 b x 16 g
            const int lg = tid >> 7, idx = tid & 127;
            const int j = idx >> 4, k = idx & 15;
            const int grp = bid * 2 + lg;
            const int bq = grp & 3, gs = grp >> 2;
            hsh[lg][j][k] = hidden[(size_t)(bq * 8 + j) * H + gs * 16 + k];
        }
        __syncthreads();

        const int lg = tid >> 8, hq = tid & 255;
        const int grp = bid * 2 + lg;
        const int bq = grp & 3, gs = grp >> 2;
        const int g0 = gs * 16;
        const float4* __restrict__ W4 = (const float4*)W;

        float4 acc[8];
        #pragma unroll
        for (int j = 0; j < 8; j++) acc[j] = make_float4(0.f, 0.f, 0.f, 0.f);

        #pragma unroll
        for (int r = 0; r < 2; r++) {
            float4 w[8];                       // 8 loads in flight
            #pragma unroll
            for (int i = 0; i < 8; i++)
                w[i] = W4[(size_t)(g0 + r * 8 + i) * H4 + hq];
            #pragma unroll
            for (int i = 0; i < 8; i++) {
                #pragma unroll
                for (int j = 0; j < 8; j++) {
                    const float hv = hsh[lg][j][r * 8 + i];
                    acc[j].x += w[i].x * hv; acc[j].y += w[i].y * hv;
                    acc[j].z += w[i].z * hv; acc[j].w += w[i].w * hv;
                }
            }
        }
        #pragma unroll
        for (int j = 0; j < 8; j++)
            *(float4*)&g_vpart[gs][bq * 8 + j][hq * 4] = acc[j];
    }
    grid_sync();

    // ---------------- Phase 2: quarter reduce ----------------
    // t < 32768 (blocks 0..63): q = t>>13, f = t&8191 -> (b, h4).
    {
        const int t = bid * NT + tid;
        if (t < 32768) {
            const int q = t >> 13, f = t & 8191;
            const int b = f >> 8, h4 = f & 255;
            const int p0 = q * 16;
            float4 s = make_float4(0.f, 0.f, 0.f, 0.f);
            #pragma unroll
            for (int r = 0; r < 2; r++) {
                float4 v[8];
                #pragma unroll
                for (int i = 0; i < 8; i++)
                    v[i] = *(const float4*)&g_vpart[p0 + r * 8 + i][b][h4 * 4];
                #pragma unroll
                for (int i = 0; i < 8; i++) {
                    s.x += v[i].x; s.y += v[i].y; s.z += v[i].z; s.w += v[i].w;
                }
            }
            *(float4*)&g_vq[q][b][h4 * 4] = s;
        }
    }
    grid_sync();

    // ---------------- Phase 3: energies ----------------
    // 2048 items = b(32) x 64 l-tiles of 32 l. Strided over 148 blocks.
    {
        const int warp = tid >> 5, lane = tid & 31;
        const float4* __restrict__ enc4 = (const float4*)enc;

        for (int item = bid; item < 2048; item += NB) {
            const int b  = item >> 6;
            const int l0 = (item & 63) * 32;

            __syncthreads();                  // vsh safe to overwrite
            if (tid < 256) {
                float4 s = make_float4(0.f, 0.f, 0.f, 0.f);
                #pragma unroll
                for (int q = 0; q < 4; q++) {
                    const float4 v = *(const float4*)&g_vq[q][b][tid * 4];
                    s.x += v.x; s.y += v.y; s.z += v.z; s.w += v.w;
                }
                vsh[tid] = s;
            }
            __syncthreads();

            const int la = l0 + warp * 2;     // 2 l's per warp
            const size_t b0 = ((size_t)(la + 0) * B + b) * H4;
            const size_t b1 = ((size_t)(la + 1) * B + b) * H4;

            float a0 = 0.f, a1 = 0.f;
            #pragma unroll
            for (int k = 0; k < 8; k++) {
                const float4 v  = vsh[k * 32 + lane];
                const float4 e0 = __ldcs(&enc4[b0 + k * 32 + lane]);
                const float4 e1 = __ldcs(&enc4[b1 + k * 32 + lane]);
                a0 += e0.x * v.x + e0.y * v.y + e0.z * v.z + e0.w * v.w;
                a1 += e1.x * v.x + e1.y * v.y + e1.z * v.z + e1.w * v.w;
            }
            #pragma unroll
            for (int s = 16; s; s >>= 1) {
                a0 += __shfl_down_sync(0xffffffffu, a0, s);
                a1 += __shfl_down_sync(0xffffffffu, a1, s);
            }
            if (lane == 0) {
                g_energy[b][la + 0] = a0;
                g_energy[b][la + 1] = a1;
                atomicMax(&g_maxu[b], enc_f(fmaxf(a0, a1)));  // deterministic
            }
        }
    }
    grid_sync();

    // ---------------- Phase 4: masked softmax ----------------
    if (bid < B) {
        const int b   = bid;
        const int len = lengths[b];
        const int l0  = tid * 4;

        const float4 e = ((const float4*)&g_energy[b][0])[tid];
        const float mx = dec_f(g_maxu[b]);

        float4 x;
        x.x = (l0 + 0 < len) ? expf(e.x - mx) : 0.f;
        x.y = (l0 + 1 < len) ? expf(e.y - mx) : 0.f;
        x.z = (l0 + 2 < len) ? expf(e.z - mx) : 0.f;
        x.w = (l0 + 3 < len) ? expf(e.w - mx) : 0.f;

        float sum = x.x + x.y + x.z + x.w;
        #pragma unroll
        for (int s = 16; s; s >>= 1)
            sum += __shfl_xor_sync(0xffffffffu, sum, s);
        if ((tid & 31) == 0) red_s[tid >> 5] = sum;
        __syncthreads();
        if (tid < 32) {
            float m = (tid < 16) ? red_s[tid] : 0.f;
            #pragma unroll
            for (int s = 8; s; s >>= 1)
                m += __shfl_xor_sync(0xffffffffu, m, s);
            if (tid == 0) red_s[0] = m;
        }
        __syncthreads();
        const float inv = 1.f / red_s[0];

        x.x *= inv; x.y *= inv; x.z *= inv; x.w *= inv;
        ((float4*)(out + (size_t)b * L))[tid] = x;
    }
}

// ---------------------------------------------------------------------------
extern "C" void kernel_launch(void* const* d_in, const int* in_sizes, int n_in,
                              void* d_out, int out_size) {
    const float* hidden  = (const float*)d_in[0];   // [1,B,H]
    const float* enc     = (const float*)d_in[1];   // [L,B,H]
    const float* W       = (const float*)d_in[2];   // [H,H]
    // d_in[3] = bias — provably cancels in softmax, unused
    const int*   lengths = (const int*)d_in[4];     // [B]
    float* out = (float*)d_out;                     // [B,1,L]

    fused_attn<<<NB, NT>>>(hidden, enc, W, lengths, out);
}

// round 10
// speedup vs baseline: 1.0771x; 1.0771x over previous
#include <cuda_runtime.h>

#define L 2048
#define B 32
#define H 1024
#define H4 256
#define NB 148
#define NT 1024

// Scratch (allocation-free rule: __device__ globals)
__device__ float g_vpart[64][B][H];      // 8 MB partials (16 g each)
__device__ float g_vq[4][B][H];          // 512 KB quarter-reduced v
__device__ float g_energy[B][L];         // 256 KB energies
__device__ unsigned g_maxu[B];           // monotone-encoded per-b max
__device__ unsigned g_bar;               // monotonic grid barrier counter

__device__ __forceinline__ unsigned enc_f(float x) {
    unsigned u = __float_as_uint(x);
    return (x >= 0.f) ? (u | 0x80000000u) : ~u;
}
__device__ __forceinline__ float dec_f(unsigned e) {
    return (e & 0x80000000u) ? __uint_as_float(e ^ 0x80000000u)
                             : __uint_as_float(~e);
}

// Software grid barrier: monotonic counter, no reset across replays.
__device__ __forceinline__ void grid_sync() {
    __syncthreads();
    if (threadIdx.x == 0) {
        __threadfence();
        const unsigned old = atomicAdd(&g_bar, 1u);
        const unsigned tgt = (old / NB + 1u) * NB;
        while (*(volatile unsigned*)&g_bar < tgt) __nanosleep(64);
        __threadfence();
    }
    __syncthreads();
}

__global__ void __launch_bounds__(NT, 1)
fused_attn(const float* __restrict__ hidden,
           const float* __restrict__ enc,
           const float* __restrict__ W,
           const int*   __restrict__ lengths,
           float* __restrict__ out) {
    const int tid = threadIdx.x;
    const int bid = blockIdx.x;

    __shared__ float  hsh[4][4][16];     // P1 hidden stage (1 KB)
    __shared__ float4 vsh[H4];           // P3 v row (4 KB)
    __shared__ float  red_s[32];         // P4 reduction

    if (bid == 0 && tid < B) g_maxu[tid] = 0u;   // encoded -inf (pre-sync)

    // ---------------- Phase 1: v partials ----------------
    // 512 groups = 64 g-slices x 8 b-quads; blocks 0..127, 4 groups each.
    // Thread: hq (float4 col), 16 g, 4 b-accumulators; 4-deep W batches.
    if (bid < 128) {
        if (tid < 256) {   // stage hidden: 4 lg x 4 b x 16 g
            const int lg = tid >> 6, j = (tid >> 4) & 3, k = tid & 15;
            const int grp = bid * 4 + lg;
            const int gs = grp >> 3, bq = grp & 7;
            hsh[lg][j][k] = hidden[(size_t)(bq * 4 + j) * H + gs * 16 + k];
        }
        __syncthreads();

        const int lg = tid >> 8, hq = tid & 255;
        const int grp = bid * 4 + lg;
        const int gs = grp >> 3, bq = grp & 7;
        const int g0 = gs * 16, b0 = bq * 4;
        const float4* __restrict__ W4 = (const float4*)W;

        float4 acc[4];
        #pragma unroll
        for (int j = 0; j < 4; j++) acc[j] = make_float4(0.f, 0.f, 0.f, 0.f);

        #pragma unroll
        for (int r = 0; r < 4; r++) {
            float4 w[4];                       // 4 loads in flight (16 regs)
            #pragma unroll
            for (int i = 0; i < 4; i++)
                w[i] = W4[(size_t)(g0 + r * 4 + i) * H4 + hq];
            #pragma unroll
            for (int i = 0; i < 4; i++) {
                #pragma unroll
                for (int j = 0; j < 4; j++) {
                    const float hv = hsh[lg][j][r * 4 + i];
                    acc[j].x += w[i].x * hv; acc[j].y += w[i].y * hv;
                    acc[j].z += w[i].z * hv; acc[j].w += w[i].w * hv;
                }
            }
        }
        #pragma unroll
        for (int j = 0; j < 4; j++)
            *(float4*)&g_vpart[gs][b0 + j][hq * 4] = acc[j];
    }
    grid_sync();

    // ---------------- Phase 2: quarter reduce ----------------
    // t < 32768 (blocks 0..31): q = t>>13, f = t&8191 -> (b, h4).
    {
        const int t = bid * NT + tid;
        if (t < 32768) {
            const int q = t >> 13, f = t & 8191;
            const int b = f >> 8, h4 = f & 255;
            const int p0 = q * 16;
            float4 s = make_float4(0.f, 0.f, 0.f, 0.f);
            #pragma unroll
            for (int r = 0; r < 4; r++) {
                float4 v[4];
                #pragma unroll
                for (int i = 0; i < 4; i++)
                    v[i] = *(const float4*)&g_vpart[p0 + r * 4 + i][b][h4 * 4];
                #pragma unroll
                for (int i = 0; i < 4; i++) {
                    s.x += v[i].x; s.y += v[i].y; s.z += v[i].z; s.w += v[i].w;
                }
            }
            *(float4*)&g_vq[q][b][h4 * 4] = s;
        }
    }
    grid_sync();

    // ---------------- Phase 3: energies (length-pruned) ----------------
    // 1024 items = b(32) x 32 tiles of 64 l; 32 warps x 2 l each.
    // Rows l >= lengths[b] are NEVER read: their energies are masked to 0
    // downstream, so skipping them is exact (saves ~25% of enc traffic).
    {
        const int warp = tid >> 5, lane = tid & 31;
        const float4* __restrict__ enc4 = (const float4*)enc;

        for (int item = bid; item < 1024; item += NB) {
            const int b   = item >> 5;
            const int len = lengths[b];
            const int l0  = (item & 31) * 64;
            if (l0 >= len) continue;          // uniform per block: safe skip

            __syncthreads();                  // vsh safe to overwrite
            if (tid < 256) {
                float4 s = make_float4(0.f, 0.f, 0.f, 0.f);
                #pragma unroll
                for (int q = 0; q < 4; q++) {
                    const float4 v = *(const float4*)&g_vq[q][b][tid * 4];
                    s.x += v.x; s.y += v.y; s.z += v.z; s.w += v.w;
                }
                vsh[tid] = s;
            }
            __syncthreads();

            const int la = l0 + warp * 2;     // 2 l's per warp
            const bool v0 = (la     < len);
            const bool v1 = (la + 1 < len);
            if (!v0) continue;                // warp-uniform

            const size_t ba = ((size_t)(la + 0) * B + b) * H4;
            const size_t bb = ((size_t)(la + 1) * B + b) * H4;

            float a0 = 0.f, a1 = 0.f;
            if (v1) {
                #pragma unroll
                for (int k = 0; k < 8; k++) {
                    const float4 v  = vsh[k * 32 + lane];
                    const float4 e0 = __ldcs(&enc4[ba + k * 32 + lane]);
                    const float4 e1 = __ldcs(&enc4[bb + k * 32 + lane]);
                    a0 += e0.x * v.x + e0.y * v.y + e0.z * v.z + e0.w * v.w;
                    a1 += e1.x * v.x + e1.y * v.y + e1.z * v.z + e1.w * v.w;
                }
            } else {
                #pragma unroll
                for (int k = 0; k < 8; k++) {
                    const float4 v  = vsh[k * 32 + lane];
                    const float4 e0 = __ldcs(&enc4[ba + k * 32 + lane]);
                    a0 += e0.x * v.x + e0.y * v.y + e0.z * v.z + e0.w * v.w;
                }
            }
            #pragma unroll
            for (int s = 16; s; s >>= 1) {
                a0 += __shfl_down_sync(0xffffffffu, a0, s);
                a1 += __shfl_down_sync(0xffffffffu, a1, s);
            }
            if (lane == 0) {
                g_energy[b][la] = a0;
                float m = a0;
                if (v1) { g_energy[b][la + 1] = a1; m = fmaxf(m, a1); }
                atomicMax(&g_maxu[b], enc_f(m));   // max over valid only
            }
        }
    }
    grid_sync();

    // ---------------- Phase 4: masked softmax ----------------
    // blocks 0..31, 1024 threads, float2 per thread (invalid lanes: e unused).
    if (bid < B) {
        const int b   = bid;
        const int len = lengths[b];
        const int l0  = tid * 2;

        const float2 e = ((const float2*)&g_energy[b][0])[tid];
        const float mx = dec_f(g_maxu[b]);

        float x0 = (l0 + 0 < len) ? expf(e.x - mx) : 0.f;
        float x1 = (l0 + 1 < len) ? expf(e.y - mx) : 0.f;

        float sum = x0 + x1;
        #pragma unroll
        for (int s = 16; s; s >>= 1)
            sum += __shfl_xor_sync(0xffffffffu, sum, s);
        if ((tid & 31) == 0) red_s[tid >> 5] = sum;
        __syncthreads();
        if (tid < 32) {
            float m = red_s[tid];
            #pragma unroll
            for (int s = 16; s; s >>= 1)
                m += __shfl_xor_sync(0xffffffffu, m, s);
            if (tid == 0) red_s[0] = m;
        }
        __syncthreads();
        const float inv = 1.f / red_s[0];

        float2 x = make_float2(x0 * inv, x1 * inv);
        ((float2*)(out + (size_t)b * L))[tid] = x;
    }
}

// ---------------------------------------------------------------------------
extern "C" void kernel_launch(void* const* d_in, const int* in_sizes, int n_in,
                              void* d_out, int out_size) {
    const float* hidden  = (const float*)d_in[0];   // [1,B,H]
    const float* enc     = (const float*)d_in[1];   // [L,B,H]
    const float* W       = (const float*)d_in[2];   // [H,H]
    // d_in[3] = bias — provably cancels in softmax, unused
    const int*   lengths = (const int*)d_in[4];     // [B]
    float* out = (float*)d_out;                     // [B,1,L]

    fused_attn<<<NB, NT>>>(hidden, enc, W, lengths, out);
}

// round 11
// speedup vs baseline: 1.1521x; 1.0696x over previous
#include <cuda_runtime.h>

#define L 2048
#define B 32
#define H 1024
#define H4 256
#define NB 148
#define NT 1024
#define NITEMS 1024   // 32 b x 32 tiles of 64 l

// Scratch (allocation-free rule: __device__ globals)
__device__ float g_vpart[64][B][H];      // 8 MB partials (16 g each)
__device__ float g_vq[4][B][H];          // 512 KB quarter-reduced v
__device__ float g_energy[B][L];         // 256 KB energies
__device__ unsigned g_maxu[B];           // monotone-encoded per-b max
__device__ unsigned g_bar;               // monotonic grid barrier counter
__device__ unsigned g_item;              // P3 dynamic work counter

__device__ __forceinline__ unsigned enc_f(float x) {
    unsigned u = __float_as_uint(x);
    return (x >= 0.f) ? (u | 0x80000000u) : ~u;
}
__device__ __forceinline__ float dec_f(unsigned e) {
    return (e & 0x80000000u) ? __uint_as_float(e ^ 0x80000000u)
                             : __uint_as_float(~e);
}

// Software grid barrier: monotonic counter, no reset across replays.
__device__ __forceinline__ void grid_sync() {
    __syncthreads();
    if (threadIdx.x == 0) {
        __threadfence();
        const unsigned old = atomicAdd(&g_bar, 1u);
        const unsigned tgt = (old / NB + 1u) * NB;
        while (*(volatile unsigned*)&g_bar < tgt) __nanosleep(64);
        __threadfence();
    }
    __syncthreads();
}

__global__ void __launch_bounds__(NT, 1)
fused_attn(const float* __restrict__ hidden,
           const float* __restrict__ enc,
           const float* __restrict__ W,
           const int*   __restrict__ lengths,
           float* __restrict__ out) {
    const int tid = threadIdx.x;
    const int bid = blockIdx.x;

    __shared__ float  hsh[4][4][16];     // P1 hidden stage (1 KB)
    __shared__ float4 vsh[H4];           // P3 v row (4 KB)
    __shared__ float  red_s[32];         // P4 reduction
    __shared__ int    sh_item;           // P3 work broadcast

    if (bid == 0 && tid == 0) g_item = 0u;       // reset P3 counter (pre-sync)
    if (bid == 0 && tid < B)  g_maxu[tid] = 0u;  // encoded -inf (pre-sync)

    // ---------------- Phase 1: v partials ----------------
    // 512 groups = 64 g-slices x 8 b-quads; blocks 0..127, 4 groups each.
    if (bid < 128) {
        if (tid < 256) {   // stage hidden: 4 lg x 4 b x 16 g
            const int lg = tid >> 6, j = (tid >> 4) & 3, k = tid & 15;
            const int grp = bid * 4 + lg;
            const int gs = grp >> 3, bq = grp & 7;
            hsh[lg][j][k] = hidden[(size_t)(bq * 4 + j) * H + gs * 16 + k];
        }
        __syncthreads();

        const int lg = tid >> 8, hq = tid & 255;
        const int grp = bid * 4 + lg;
        const int gs = grp >> 3, bq = grp & 7;
        const int g0 = gs * 16, b0 = bq * 4;
        const float4* __restrict__ W4 = (const float4*)W;

        float4 acc[4];
        #pragma unroll
        for (int j = 0; j < 4; j++) acc[j] = make_float4(0.f, 0.f, 0.f, 0.f);

        #pragma unroll
        for (int r = 0; r < 4; r++) {
            float4 w[4];                       // 4 loads in flight
            #pragma unroll
            for (int i = 0; i < 4; i++)
                w[i] = W4[(size_t)(g0 + r * 4 + i) * H4 + hq];
            #pragma unroll
            for (int i = 0; i < 4; i++) {
                #pragma unroll
                for (int j = 0; j < 4; j++) {
                    const float hv = hsh[lg][j][r * 4 + i];
                    acc[j].x += w[i].x * hv; acc[j].y += w[i].y * hv;
                    acc[j].z += w[i].z * hv; acc[j].w += w[i].w * hv;
                }
            }
        }
        #pragma unroll
        for (int j = 0; j < 4; j++)
            *(float4*)&g_vpart[gs][b0 + j][hq * 4] = acc[j];
    }
    grid_sync();

    // ---------------- Phase 2: quarter reduce ----------------
    {
        const int t = bid * NT + tid;
        if (t < 32768) {
            const int q = t >> 13, f = t & 8191;
            const int b = f >> 8, h4 = f & 255;
            const int p0 = q * 16;
            float4 s = make_float4(0.f, 0.f, 0.f, 0.f);
            #pragma unroll
            for (int r = 0; r < 4; r++) {
                float4 v[4];
                #pragma unroll
                for (int i = 0; i < 4; i++)
                    v[i] = *(const float4*)&g_vpart[p0 + r * 4 + i][b][h4 * 4];
                #pragma unroll
                for (int i = 0; i < 4; i++) {
                    s.x += v[i].x; s.y += v[i].y; s.z += v[i].z; s.w += v[i].w;
                }
            }
            *(float4*)&g_vq[q][b][h4 * 4] = s;
        }
    }
    grid_sync();

    // ---------------- Phase 3: energies (length-pruned, work-stealing) ----
    // Items: b(32) x 32 tiles of 64 l, grabbed dynamically for load balance.
    // Rows l >= lengths[b] are never read (skipped items are exact: their
    // energies are masked to 0 downstream).
    {
        const int warp = tid >> 5, lane = tid & 31;
        const float4* __restrict__ enc4 = (const float4*)enc;

        for (;;) {
            if (tid == 0) sh_item = (int)atomicAdd(&g_item, 1u);
            __syncthreads();                  // publish sh_item; prior compute done
            const int item = sh_item;
            __syncthreads();                  // all read sh_item before next grab
            if (item >= NITEMS) break;

            const int b   = item >> 5;
            const int len = lengths[b];
            const int l0  = (item & 31) * 64;
            if (l0 >= len) continue;          // block-uniform: safe skip

            if (tid < 256) {                  // vsh overwrite safe post-publish sync
                float4 s = make_float4(0.f, 0.f, 0.f, 0.f);
                #pragma unroll
                for (int q = 0; q < 4; q++) {
                    const float4 v = *(const float4*)&g_vq[q][b][tid * 4];
                    s.x += v.x; s.y += v.y; s.z += v.z; s.w += v.w;
                }
                vsh[tid] = s;
            }
            __syncthreads();

            const int la = l0 + warp * 2;     // 2 l's per warp
            const bool v1 = (la + 1 < len);
            if (la >= len) continue;          // warp-uniform tail skip

            const size_t ba = ((size_t)(la + 0) * B + b) * H4;
            const size_t bb = ((size_t)(la + 1) * B + b) * H4;

            float a0 = 0.f, a1 = 0.f;
            if (v1) {
                #pragma unroll
                for (int k = 0; k < 8; k++) {
                    const float4 v  = vsh[k * 32 + lane];
                    const float4 e0 = __ldcs(&enc4[ba + k * 32 + lane]);
                    const float4 e1 = __ldcs(&enc4[bb + k * 32 + lane]);
                    a0 += e0.x * v.x + e0.y * v.y + e0.z * v.z + e0.w * v.w;
                    a1 += e1.x * v.x + e1.y * v.y + e1.z * v.z + e1.w * v.w;
                }
            } else {
                #pragma unroll
                for (int k = 0; k < 8; k++) {
                    const float4 v  = vsh[k * 32 + lane];
                    const float4 e0 = __ldcs(&enc4[ba + k * 32 + lane]);
                    a0 += e0.x * v.x + e0.y * v.y + e0.z * v.z + e0.w * v.w;
                }
            }
            #pragma unroll
            for (int s = 16; s; s >>= 1) {
                a0 += __shfl_down_sync(0xffffffffu, a0, s);
                a1 += __shfl_down_sync(0xffffffffu, a1, s);
            }
            if (lane == 0) {
                g_energy[b][la] = a0;
                float m = a0;
                if (v1) { g_energy[b][la + 1] = a1; m = fmaxf(m, a1); }
                atomicMax(&g_maxu[b], enc_f(m));   // max over valid only
            }
        }
    }
    grid_sync();

    // ---------------- Phase 4: masked softmax ----------------
    if (bid < B) {
        const int b   = bid;
        const int len = lengths[b];
        const int l0  = tid * 2;

        const float2 e = ((const float2*)&g_energy[b][0])[tid];
        const float mx = dec_f(g_maxu[b]);

        float x0 = (l0 + 0 < len) ? expf(e.x - mx) : 0.f;
        float x1 = (l0 + 1 < len) ? expf(e.y - mx) : 0.f;

        float sum = x0 + x1;
        #pragma unroll
        for (int s = 16; s; s >>= 1)
            sum += __shfl_xor_sync(0xffffffffu, sum, s);
        if ((tid & 31) == 0) red_s[tid >> 5] = sum;
        __syncthreads();
        if (tid < 32) {
            float m = red_s[tid];
            #pragma unroll
            for (int s = 16; s; s >>= 1)
                m += __shfl_xor_sync(0xffffffffu, m, s);
            if (tid == 0) red_s[0] = m;
        }
        __syncthreads();
        const float inv = 1.f / red_s[0];

        float2 x = make_float2(x0 * inv, x1 * inv);
        ((float2*)(out + (size_t)b * L))[tid] = x;
    }
}

// ---------------------------------------------------------------------------
extern "C" void kernel_launch(void* const* d_in, const int* in_sizes, int n_in,
                              void* d_out, int out_size) {
    const float* hidden  = (const float*)d_in[0];   // [1,B,H]
    const float* enc     = (const float*)d_in[1];   // [L,B,H]
    const float* W       = (const float*)d_in[2];   // [H,H]
    // d_in[3] = bias — provably cancels in softmax, unused
    const int*   lengths = (const int*)d_in[4];     // [B]
    float* out = (float*)d_out;                     // [B,1,L]

    fused_attn<<<NB, NT>>>(hidden, enc, W, lengths, out);
}